// round 5
// baseline (speedup 1.0000x reference)
#include <cuda_runtime.h>
#include <cuda_bf16.h>

#define N_NODES 100000
#define N_EDGES 1600000
#define D 64            // feature dim == units

// Scratch (no allocations allowed in kernel_launch)
__device__ float g_deg[N_NODES];
__device__ float g_dinv[N_NODES];
__device__ float g_pool[N_NODES * D];

// ---------------------------------------------------------------------------
// 1) zero pooled + degree (must run every launch: graph replays reuse scratch)
// ---------------------------------------------------------------------------
__global__ void zero_kernel() {
    int i = blockIdx.x * blockDim.x + threadIdx.x;
    int total4 = (N_NODES * D) / 4;
    if (i < total4) {
        ((float4*)g_pool)[i] = make_float4(0.f, 0.f, 0.f, 0.f);
    }
    if (i < N_NODES) {
        g_deg[i] = 0.f;
    }
}

// ---------------------------------------------------------------------------
// 2) in-degree by target
// ---------------------------------------------------------------------------
__global__ void degree_kernel(const int* __restrict__ tgt) {
    int e = blockIdx.x * blockDim.x + threadIdx.x;
    if (e < N_EDGES) {
        atomicAdd(&g_deg[tgt[e]], 1.0f);   // compiles to RED (no return use)
    }
}

// ---------------------------------------------------------------------------
// 3) dinv = rsqrt(deg)
// ---------------------------------------------------------------------------
__global__ void dinv_kernel() {
    int i = blockIdx.x * blockDim.x + threadIdx.x;
    if (i < N_NODES) {
        g_dinv[i] = rsqrtf(g_deg[i]);
    }
}

// ---------------------------------------------------------------------------
// 4) scatter: pooled[tgt] += dinv[src] * x[src]
//    16 threads per edge, one float4 (16B) chunk each, vector RED.
// ---------------------------------------------------------------------------
__global__ void scatter_kernel(const float* __restrict__ x,
                               const int* __restrict__ src,
                               const int* __restrict__ tgt) {
    int t = blockIdx.x * blockDim.x + threadIdx.x;   // [0, N_EDGES*16)
    int e = t >> 4;
    int c = t & 15;
    if (e >= N_EDGES) return;

    int s = src[e];
    int d = tgt[e];
    float sc = g_dinv[s];

    float4 v = ((const float4*)x)[s * (D / 4) + c];
    v.x *= sc; v.y *= sc; v.z *= sc; v.w *= sc;

    float* p = &g_pool[d * D + c * 4];
    asm volatile("red.global.add.v4.f32 [%0], {%1, %2, %3, %4};"
                 :: "l"(p), "f"(v.x), "f"(v.y), "f"(v.z), "f"(v.w)
                 : "memory");
}

// ---------------------------------------------------------------------------
// 5) out = relu((dinv[i] * pooled[i]) @ W + b), one thread per node
// ---------------------------------------------------------------------------
__global__ void __launch_bounds__(128) gemm_kernel(const float* __restrict__ W,
                                                   const float* __restrict__ b,
                                                   float* __restrict__ out) {
    __shared__ float Ws[D * D];   // W[k][j] at k*64+j (row-major, as given)
    __shared__ float bs[D];

    int tid = threadIdx.x;
    for (int i = tid; i < D * D; i += blockDim.x) Ws[i] = W[i];
    if (tid < D) bs[tid] = b[tid];
    __syncthreads();

    int node = blockIdx.x * blockDim.x + tid;
    if (node >= N_NODES) return;

    float sc = g_dinv[node];

    float4 acc[D / 4];
    #pragma unroll
    for (int j = 0; j < D / 4; j++) acc[j] = ((const float4*)bs)[j];

    const float4* prow4 = (const float4*)&g_pool[node * D];

    #pragma unroll
    for (int k4 = 0; k4 < D / 4; k4++) {
        float4 p4 = prow4[k4];
        p4.x *= sc; p4.y *= sc; p4.z *= sc; p4.w *= sc;
        float pk[4] = {p4.x, p4.y, p4.z, p4.w};
        #pragma unroll
        for (int kk = 0; kk < 4; kk++) {
            float pv = pk[kk];
            const float4* wrow = (const float4*)&Ws[(k4 * 4 + kk) * D];
            #pragma unroll
            for (int j = 0; j < D / 4; j++) {
                float4 w = wrow[j];   // broadcast LDS.128 (all lanes same addr)
                acc[j].x += pv * w.x;
                acc[j].y += pv * w.y;
                acc[j].z += pv * w.z;
                acc[j].w += pv * w.w;
            }
        }
    }

    float4* orow = (float4*)&out[node * D];
    #pragma unroll
    for (int j = 0; j < D / 4; j++) {
        float4 a = acc[j];
        a.x = fmaxf(a.x, 0.f);
        a.y = fmaxf(a.y, 0.f);
        a.z = fmaxf(a.z, 0.f);
        a.w = fmaxf(a.w, 0.f);
        orow[j] = a;
    }
}

// ---------------------------------------------------------------------------
// launch
// ---------------------------------------------------------------------------
extern "C" void kernel_launch(void* const* d_in, const int* in_sizes, int n_in,
                              void* d_out, int out_size) {
    const float* x   = (const float*)d_in[0];   // [N_NODES, 64]
    const float* W   = (const float*)d_in[1];   // [64, 64]
    const float* b   = (const float*)d_in[2];   // [64]
    const int*   src = (const int*)d_in[3];     // [N_EDGES]
    const int*   tgt = (const int*)d_in[4];     // [N_EDGES]
    float* out = (float*)d_out;                 // [N_NODES, 64]

    {   // zero pool (1.6M float4) + deg
        int threads = 256;
        int blocks = (N_NODES * D / 4 + threads - 1) / threads;
        zero_kernel<<<blocks, threads>>>();
    }
    {   // degree
        int threads = 256;
        int blocks = (N_EDGES + threads - 1) / threads;
        degree_kernel<<<blocks, threads>>>(tgt);
    }
    {   // dinv
        int threads = 256;
        int blocks = (N_NODES + threads - 1) / threads;
        dinv_kernel<<<blocks, threads>>>();
    }
    {   // scatter
        int threads = 256;
        long long tot = (long long)N_EDGES * 16;
        int blocks = (int)((tot + threads - 1) / threads);
        scatter_kernel<<<blocks, threads>>>(x, src, tgt);
    }
    {   // gemm + relu
        int threads = 128;
        int blocks = (N_NODES + threads - 1) / threads;
        gemm_kernel<<<blocks, threads>>>(W, b, out);
    }
}

// round 8
// speedup vs baseline: 1.0454x; 1.0454x over previous
#include <cuda_runtime.h>
#include <cuda_bf16.h>

#define N_NODES 100000
#define N_EDGES 1600000
#define D 64
#define SCAN_B 1024
#define NB_SCAN ((N_NODES + SCAN_B - 1) / SCAN_B)   // 98

// Scratch (__device__ globals; no allocations allowed)
__device__ int   g_deg[N_NODES];
__device__ int   g_off[N_NODES];
__device__ int   g_cursor[N_NODES];
__device__ int   g_bsum[NB_SCAN];
__device__ int   g_bpref[NB_SCAN];
__device__ float g_dinv[N_NODES];
__device__ int   g_csr[N_EDGES];

// ---------------------------------------------------------------------------
// 0) zero degree (graph replays reuse scratch)
// ---------------------------------------------------------------------------
__global__ void zero_deg_kernel() {
    int i = blockIdx.x * blockDim.x + threadIdx.x;
    if (i < N_NODES) g_deg[i] = 0;
}

// ---------------------------------------------------------------------------
// 1) in-degree histogram by target
// ---------------------------------------------------------------------------
__global__ void degree_kernel(const int* __restrict__ tgt) {
    int e = blockIdx.x * blockDim.x + threadIdx.x;
    if (e < N_EDGES) atomicAdd(&g_deg[tgt[e]], 1);
}

// ---------------------------------------------------------------------------
// 2a) per-block exclusive scan of degrees
// ---------------------------------------------------------------------------
__global__ void scan1_kernel() {
    __shared__ int s[SCAN_B];
    int gid = blockIdx.x * SCAN_B + threadIdx.x;
    int v = (gid < N_NODES) ? g_deg[gid] : 0;
    s[threadIdx.x] = v;
    __syncthreads();
    for (int ofs = 1; ofs < SCAN_B; ofs <<= 1) {
        int t = (threadIdx.x >= ofs) ? s[threadIdx.x - ofs] : 0;
        __syncthreads();
        s[threadIdx.x] += t;
        __syncthreads();
    }
    if (gid < N_NODES) g_off[gid] = s[threadIdx.x] - v;   // exclusive
    if (threadIdx.x == SCAN_B - 1) g_bsum[blockIdx.x] = s[SCAN_B - 1];
}

// ---------------------------------------------------------------------------
// 2b) scan of block sums (single block, 128 >= NB_SCAN)
// ---------------------------------------------------------------------------
__global__ void scan2_kernel() {
    __shared__ int s[128];
    int v = (threadIdx.x < NB_SCAN) ? g_bsum[threadIdx.x] : 0;
    s[threadIdx.x] = v;
    __syncthreads();
    for (int ofs = 1; ofs < 128; ofs <<= 1) {
        int t = (threadIdx.x >= ofs) ? s[threadIdx.x - ofs] : 0;
        __syncthreads();
        s[threadIdx.x] += t;
        __syncthreads();
    }
    if (threadIdx.x < NB_SCAN) g_bpref[threadIdx.x] = s[threadIdx.x] - v;
}

// ---------------------------------------------------------------------------
// 2c) add block prefixes, zero cursors, compute dinv
// ---------------------------------------------------------------------------
__global__ void scan3_kernel() {
    int i = blockIdx.x * blockDim.x + threadIdx.x;
    if (i < N_NODES) {
        g_off[i] += g_bpref[i >> 10];
        g_cursor[i] = 0;
        g_dinv[i] = rsqrtf((float)g_deg[i]);
    }
}

// ---------------------------------------------------------------------------
// 3) CSR fill: bucket src indices by target
// ---------------------------------------------------------------------------
__global__ void fill_kernel(const int* __restrict__ src,
                            const int* __restrict__ tgt) {
    int e = blockIdx.x * blockDim.x + threadIdx.x;
    if (e < N_EDGES) {
        int t = tgt[e];
        int p = g_off[t] + atomicAdd(&g_cursor[t], 1);
        g_csr[p] = src[e];
    }
}

// ---------------------------------------------------------------------------
// 4) fused gather + scale + GEMM + bias + ReLU
//    16 lanes per node (lane c owns float4 chunk c), 16 nodes per 256-thr block.
//    NOTE: shfl member mask is the 16-lane SEGMENT mask — the two half-warps
//    in a warp have different deg and legally diverge.
// ---------------------------------------------------------------------------
__global__ void __launch_bounds__(256) fused_kernel(const float* __restrict__ x,
                                                    const float* __restrict__ W,
                                                    const float* __restrict__ b,
                                                    float* __restrict__ out) {
    __shared__ float Ws[D * D];      // 16 KB
    __shared__ float bs[D];
    __shared__ float ps[16 * 68];    // per-node pooled rows, stride 68 (no bank conflicts)

    int tid = threadIdx.x;
    for (int i = tid; i < D * D; i += 256) Ws[i] = W[i];
    if (tid < D) bs[tid] = b[tid];

    int g = tid >> 4;                // local node 0..15
    int c = tid & 15;                // chunk 0..15
    int node = blockIdx.x * 16 + g;  // N_NODES = 16 * 6250 exactly — no tail

    // segment-local member mask: lanes 0-15 -> 0x0000FFFF, lanes 16-31 -> 0xFFFF0000
    const unsigned mask = 0xFFFFu << (threadIdx.x & 16);

    int off = g_off[node];
    int deg = g_deg[node];

    const float4* __restrict__ x4 = (const float4*)x;
    float4 acc = make_float4(0.f, 0.f, 0.f, 0.f);

    int base = 0;
    // full 16-edge batches: coalesced csr/dinv loads, shfl broadcast within segment
    for (; base + 16 <= deg; base += 16) {
        int   myidx = g_csr[off + base + c];
        float mydv  = g_dinv[myidx];
        #pragma unroll 8
        for (int i = 0; i < 16; i++) {
            int   idx = __shfl_sync(mask, myidx, i, 16);
            float dv  = __shfl_sync(mask, mydv,  i, 16);
            float4 v = x4[idx * (D / 4) + c];
            acc.x += dv * v.x; acc.y += dv * v.y;
            acc.z += dv * v.z; acc.w += dv * v.w;
        }
    }
    int rem = deg - base;
    if (rem > 0) {
        int   myidx = (c < rem) ? g_csr[off + base + c] : 0;
        float mydv  = (c < rem) ? g_dinv[myidx] : 0.f;
        for (int i = 0; i < rem; i++) {
            int   idx = __shfl_sync(mask, myidx, i, 16);
            float dv  = __shfl_sync(mask, mydv,  i, 16);
            float4 v = x4[idx * (D / 4) + c];
            acc.x += dv * v.x; acc.y += dv * v.y;
            acc.z += dv * v.z; acc.w += dv * v.w;
        }
    }

    // scale by dinv[node], stage pooled row to smem
    float dn = g_dinv[node];
    float* pg = &ps[g * 68 + c * 4];
    pg[0] = acc.x * dn; pg[1] = acc.y * dn;
    pg[2] = acc.z * dn; pg[3] = acc.w * dn;
    __syncthreads();

    // GEMM: out[node][c*4..c*4+3] = relu(sum_k p[k] * W[k][j] + b[j])
    float4 o = ((const float4*)bs)[c];
    const float* prow = &ps[g * 68];
    const float4* Ws4 = (const float4*)Ws;
    #pragma unroll
    for (int k = 0; k < D; k++) {
        float pv = prow[k];
        float4 w = Ws4[k * 16 + c];   // broadcast across node groups, conflict-free
        o.x += pv * w.x; o.y += pv * w.y;
        o.z += pv * w.z; o.w += pv * w.w;
    }
    o.x = fmaxf(o.x, 0.f); o.y = fmaxf(o.y, 0.f);
    o.z = fmaxf(o.z, 0.f); o.w = fmaxf(o.w, 0.f);
    ((float4*)&out[node * D])[c] = o;
}

// ---------------------------------------------------------------------------
// launch
// ---------------------------------------------------------------------------
extern "C" void kernel_launch(void* const* d_in, const int* in_sizes, int n_in,
                              void* d_out, int out_size) {
    const float* x   = (const float*)d_in[0];   // [N_NODES, 64]
    const float* W   = (const float*)d_in[1];   // [64, 64]
    const float* b   = (const float*)d_in[2];   // [64]
    const int*   src = (const int*)d_in[3];     // [N_EDGES]
    const int*   tgt = (const int*)d_in[4];     // [N_EDGES]
    float* out = (float*)d_out;                 // [N_NODES, 64]

    zero_deg_kernel<<<(N_NODES + 255) / 256, 256>>>();
    degree_kernel<<<(N_EDGES + 255) / 256, 256>>>(tgt);
    scan1_kernel<<<NB_SCAN, SCAN_B>>>();
    scan2_kernel<<<1, 128>>>();
    scan3_kernel<<<(N_NODES + 255) / 256, 256>>>();
    fill_kernel<<<(N_EDGES + 255) / 256, 256>>>(src, tgt);
    fused_kernel<<<N_NODES / 16, 256>>>(x, W, b, out);
}

// round 10
// speedup vs baseline: 1.0902x; 1.0428x over previous
#include <cuda_runtime.h>
#include <cuda_bf16.h>

#define N_NODES 100000
#define N_EDGES 1600000
#define D 64
#define SCAN_B 1024
#define NB_SCAN ((N_NODES + SCAN_B - 1) / SCAN_B)   // 98
#define FUSED_BLOCKS 592                             // 4 per SM on 148 SMs

// Scratch (__device__ globals; no allocations allowed)
__device__ int   g_deg[N_NODES];
__device__ int   g_off[N_NODES];
__device__ int   g_cursor[N_NODES];
__device__ int   g_bsum[NB_SCAN];
__device__ float g_dinv[N_NODES];
__device__ int   g_csr[N_EDGES];

// ---------------------------------------------------------------------------
// 0) zero degree + cursors (graph replays reuse scratch)
// ---------------------------------------------------------------------------
__global__ void zero_kernel() {
    int i = blockIdx.x * blockDim.x + threadIdx.x;
    if (i < N_NODES) { g_deg[i] = 0; g_cursor[i] = 0; }
}

// ---------------------------------------------------------------------------
// 1) in-degree histogram by target (int4-vectorized; N_EDGES % 4 == 0)
// ---------------------------------------------------------------------------
__global__ void degree_kernel(const int4* __restrict__ tgt4) {
    int e4 = blockIdx.x * blockDim.x + threadIdx.x;
    if (e4 < N_EDGES / 4) {
        int4 t = tgt4[e4];
        atomicAdd(&g_deg[t.x], 1);
        atomicAdd(&g_deg[t.y], 1);
        atomicAdd(&g_deg[t.z], 1);
        atomicAdd(&g_deg[t.w], 1);
    }
}

// ---------------------------------------------------------------------------
// 2a) per-block exclusive scan of degrees (block sums to g_bsum)
// ---------------------------------------------------------------------------
__global__ void scan1_kernel() {
    __shared__ int s[SCAN_B];
    int gid = blockIdx.x * SCAN_B + threadIdx.x;
    int v = (gid < N_NODES) ? g_deg[gid] : 0;
    s[threadIdx.x] = v;
    __syncthreads();
    for (int ofs = 1; ofs < SCAN_B; ofs <<= 1) {
        int t = (threadIdx.x >= ofs) ? s[threadIdx.x - ofs] : 0;
        __syncthreads();
        s[threadIdx.x] += t;
        __syncthreads();
    }
    if (gid < N_NODES) g_off[gid] = s[threadIdx.x] - v;   // exclusive
    if (threadIdx.x == SCAN_B - 1) g_bsum[blockIdx.x] = s[SCAN_B - 1];
}

// ---------------------------------------------------------------------------
// 2b) fixup: each 256-thread block reduces the g_bsum prefix it needs itself
//     (absorbs old scan2 + scan3), plus dinv compute
// ---------------------------------------------------------------------------
__global__ void scan3_kernel() {
    __shared__ int red[256];
    int i = blockIdx.x * 256 + threadIdx.x;
    int j = blockIdx.x >> 2;            // owning scan1 block (1024/256 = 4)
    int v = (threadIdx.x < j) ? g_bsum[threadIdx.x] : 0;   // j <= 97 < 256
    red[threadIdx.x] = v;
    __syncthreads();
    #pragma unroll
    for (int ofs = 128; ofs > 0; ofs >>= 1) {
        if (threadIdx.x < ofs) red[threadIdx.x] += red[threadIdx.x + ofs];
        __syncthreads();
    }
    int bpref = red[0];
    if (i < N_NODES) {
        g_off[i] += bpref;
        g_dinv[i] = rsqrtf((float)g_deg[i]);
    }
}

// ---------------------------------------------------------------------------
// 3) CSR fill: bucket src indices by target (int4-vectorized)
// ---------------------------------------------------------------------------
__global__ void fill_kernel(const int4* __restrict__ src4,
                            const int4* __restrict__ tgt4) {
    int e4 = blockIdx.x * blockDim.x + threadIdx.x;
    if (e4 < N_EDGES / 4) {
        int4 s = src4[e4];
        int4 t = tgt4[e4];
        int p;
        p = g_off[t.x] + atomicAdd(&g_cursor[t.x], 1); g_csr[p] = s.x;
        p = g_off[t.y] + atomicAdd(&g_cursor[t.y], 1); g_csr[p] = s.y;
        p = g_off[t.z] + atomicAdd(&g_cursor[t.z], 1); g_csr[p] = s.z;
        p = g_off[t.w] + atomicAdd(&g_cursor[t.w], 1); g_csr[p] = s.w;
    }
}

// ---------------------------------------------------------------------------
// 4) fused gather + scale + GEMM + bias + ReLU.
//    16 lanes per node-segment, segments fully independent after the one-time
//    W smem load: grid-stride over nodes, shfl-broadcast GEMM (no ps smem,
//    no per-node barrier). Segment-local shfl mask (half-warps diverge legally).
// ---------------------------------------------------------------------------
__global__ void __launch_bounds__(256, 4) fused_kernel(const float* __restrict__ x,
                                                       const float* __restrict__ W,
                                                       const float* __restrict__ b,
                                                       float* __restrict__ out) {
    __shared__ float Ws[D * D];      // 16 KB, loaded once per block
    int tid = threadIdx.x;
    for (int i = tid; i < D * D; i += 256) Ws[i] = W[i];
    __syncthreads();                 // only block-wide sync in the kernel

    int c = tid & 15;                                 // chunk 0..15
    const unsigned mask = 0xFFFFu << (tid & 16);      // 16-lane segment mask
    const float4 bias = ((const float4*)b)[c];        // per-lane bias, loop-invariant

    const float4* __restrict__ x4 = (const float4*)x;
    const int nsegs = FUSED_BLOCKS * 16;
    int seg = blockIdx.x * 16 + (tid >> 4);

    for (int node = seg; node < N_NODES; node += nsegs) {
        int off = g_off[node];
        int deg = g_deg[node];

        float4 acc = make_float4(0.f, 0.f, 0.f, 0.f);

        int base = 0;
        for (; base + 16 <= deg; base += 16) {
            int   myidx = g_csr[off + base + c];      // coalesced 64B/segment
            float mydv  = g_dinv[myidx];
            #pragma unroll 8
            for (int i = 0; i < 16; i++) {
                int   idx = __shfl_sync(mask, myidx, i, 16);
                float dv  = __shfl_sync(mask, mydv,  i, 16);
                float4 v = x4[idx * (D / 4) + c];
                acc.x += dv * v.x; acc.y += dv * v.y;
                acc.z += dv * v.z; acc.w += dv * v.w;
            }
        }
        int rem = deg - base;
        if (rem > 0) {
            int   myidx = (c < rem) ? g_csr[off + base + c] : 0;
            float mydv  = (c < rem) ? g_dinv[myidx] : 0.f;
            for (int i = 0; i < rem; i++) {
                int   idx = __shfl_sync(mask, myidx, i, 16);
                float dv  = __shfl_sync(mask, mydv,  i, 16);
                float4 v = x4[idx * (D / 4) + c];
                acc.x += dv * v.x; acc.y += dv * v.y;
                acc.z += dv * v.z; acc.w += dv * v.w;
            }
        }

        // scale by dinv[node]: lane i now holds pooled[4i..4i+3]
        float dn = g_dinv[node];                      // broadcast load
        acc.x *= dn; acc.y *= dn; acc.z *= dn; acc.w *= dn;

        // GEMM via shfl broadcast: out[node][4c..4c+3] = relu(sum_k p[k]*W[k][j] + b)
        float4 o = bias;
        #pragma unroll
        for (int i = 0; i < 16; i++) {
            float p0 = __shfl_sync(mask, acc.x, i, 16);
            float p1 = __shfl_sync(mask, acc.y, i, 16);
            float p2 = __shfl_sync(mask, acc.z, i, 16);
            float p3 = __shfl_sync(mask, acc.w, i, 16);
            float4 w0 = ((const float4*)&Ws[(4 * i + 0) * D])[c];
            float4 w1 = ((const float4*)&Ws[(4 * i + 1) * D])[c];
            float4 w2 = ((const float4*)&Ws[(4 * i + 2) * D])[c];
            float4 w3 = ((const float4*)&Ws[(4 * i + 3) * D])[c];
            o.x += p0 * w0.x; o.y += p0 * w0.y; o.z += p0 * w0.z; o.w += p0 * w0.w;
            o.x += p1 * w1.x; o.y += p1 * w1.y; o.z += p1 * w1.z; o.w += p1 * w1.w;
            o.x += p2 * w2.x; o.y += p2 * w2.y; o.z += p2 * w2.z; o.w += p2 * w2.w;
            o.x += p3 * w3.x; o.y += p3 * w3.y; o.z += p3 * w3.z; o.w += p3 * w3.w;
        }
        o.x = fmaxf(o.x, 0.f); o.y = fmaxf(o.y, 0.f);
        o.z = fmaxf(o.z, 0.f); o.w = fmaxf(o.w, 0.f);
        ((float4*)&out[node * D])[c] = o;
    }
}

// ---------------------------------------------------------------------------
// launch (6 kernels)
// ---------------------------------------------------------------------------
extern "C" void kernel_launch(void* const* d_in, const int* in_sizes, int n_in,
                              void* d_out, int out_size) {
    const float* x   = (const float*)d_in[0];   // [N_NODES, 64]
    const float* W   = (const float*)d_in[1];   // [64, 64]
    const float* b   = (const float*)d_in[2];   // [64]
    const int*   src = (const int*)d_in[3];     // [N_EDGES]
    const int*   tgt = (const int*)d_in[4];     // [N_EDGES]
    float* out = (float*)d_out;                 // [N_NODES, 64]

    zero_kernel<<<(N_NODES + 255) / 256, 256>>>();
    degree_kernel<<<(N_EDGES / 4 + 255) / 256, 256>>>((const int4*)tgt);
    scan1_kernel<<<NB_SCAN, SCAN_B>>>();
    scan3_kernel<<<(N_NODES + 255) / 256, 256>>>();
    fill_kernel<<<(N_EDGES / 4 + 255) / 256, 256>>>((const int4*)src, (const int4*)tgt);
    fused_kernel<<<FUSED_BLOCKS, 256>>>(x, W, b, out);
}

// round 11
// speedup vs baseline: 1.2864x; 1.1800x over previous
#include <cuda_runtime.h>
#include <cuda_bf16.h>

#define N_NODES 100000
#define N_EDGES 1600000
#define D 64
#define SCAN_B 1024
#define NB_SCAN ((N_NODES + SCAN_B - 1) / SCAN_B)   // 98

typedef unsigned long long ull;

// Scratch (__device__ globals; no allocations allowed)
__device__ int   g_deg[N_NODES];
__device__ int   g_off[N_NODES];
__device__ int   g_cursor[N_NODES];
__device__ int   g_bsum[NB_SCAN];
__device__ float g_dinv[N_NODES];
__device__ int   g_csr[N_EDGES];
__device__ float g_z[N_NODES * D];     // Z = diag(dinv) * (X @ W), 25.6 MB

// ---- packed f32x2 helpers (sm_10x; FFMA2 only reachable via PTX) ----------
__device__ __forceinline__ ull pack2(float lo, float hi) {
    ull r; asm("mov.b64 %0, {%1, %2};" : "=l"(r) : "f"(lo), "f"(hi)); return r;
}
__device__ __forceinline__ ull fma2(ull a, ull b, ull c) {   // a*b + c
    ull d; asm("fma.rn.f32x2 %0, %1, %2, %3;" : "=l"(d) : "l"(a), "l"(b), "l"(c));
    return d;
}
__device__ __forceinline__ ull mul2(ull a, ull b) {
    ull d; asm("mul.rn.f32x2 %0, %1, %2;" : "=l"(d) : "l"(a), "l"(b)); return d;
}

// ---------------------------------------------------------------------------
// 0) zero degree (graph replays reuse scratch; cursor seeded in scan3)
// ---------------------------------------------------------------------------
__global__ void zero_kernel() {
    int i = blockIdx.x * blockDim.x + threadIdx.x;
    if (i < N_NODES) g_deg[i] = 0;
}

// ---------------------------------------------------------------------------
// 1) in-degree histogram by target (int4-vectorized; N_EDGES % 4 == 0)
// ---------------------------------------------------------------------------
__global__ void degree_kernel(const int4* __restrict__ tgt4) {
    int e4 = blockIdx.x * blockDim.x + threadIdx.x;
    if (e4 < N_EDGES / 4) {
        int4 t = tgt4[e4];
        atomicAdd(&g_deg[t.x], 1);
        atomicAdd(&g_deg[t.y], 1);
        atomicAdd(&g_deg[t.z], 1);
        atomicAdd(&g_deg[t.w], 1);
    }
}

// ---------------------------------------------------------------------------
// 2a) per-block exclusive scan of degrees (block sums to g_bsum) + dinv
// ---------------------------------------------------------------------------
__global__ void scan1_kernel() {
    __shared__ int s[SCAN_B];
    int gid = blockIdx.x * SCAN_B + threadIdx.x;
    int v = (gid < N_NODES) ? g_deg[gid] : 0;
    s[threadIdx.x] = v;
    if (gid < N_NODES) g_dinv[gid] = rsqrtf((float)v);
    __syncthreads();
    for (int ofs = 1; ofs < SCAN_B; ofs <<= 1) {
        int t = (threadIdx.x >= ofs) ? s[threadIdx.x - ofs] : 0;
        __syncthreads();
        s[threadIdx.x] += t;
        __syncthreads();
    }
    if (gid < N_NODES) g_off[gid] = s[threadIdx.x] - v;   // exclusive
    if (threadIdx.x == SCAN_B - 1) g_bsum[blockIdx.x] = s[SCAN_B - 1];
}

// ---------------------------------------------------------------------------
// 2b) fixup: add block prefix (reduced locally) + seed cursor with offset
// ---------------------------------------------------------------------------
__global__ void scan3_kernel() {
    __shared__ int red[256];
    int i = blockIdx.x * 256 + threadIdx.x;
    int j = blockIdx.x >> 2;            // owning scan1 block (1024/256 = 4)
    int v = (threadIdx.x < j) ? g_bsum[threadIdx.x] : 0;   // j <= 97 < 256
    red[threadIdx.x] = v;
    __syncthreads();
    #pragma unroll
    for (int ofs = 128; ofs > 0; ofs >>= 1) {
        if (threadIdx.x < ofs) red[threadIdx.x] += red[threadIdx.x + ofs];
        __syncthreads();
    }
    int bpref = red[0];
    if (i < N_NODES) {
        int o = g_off[i] + bpref;
        g_off[i] = o;
        g_cursor[i] = o;                // fill uses cursor directly as slot
    }
}

// ---------------------------------------------------------------------------
// 3) CSR fill: bucket src indices by target (int4-vectorized, 1 atomic each)
// ---------------------------------------------------------------------------
__global__ void fill_kernel(const int4* __restrict__ src4,
                            const int4* __restrict__ tgt4) {
    int e4 = blockIdx.x * blockDim.x + threadIdx.x;
    if (e4 < N_EDGES / 4) {
        int4 s = src4[e4];
        int4 t = tgt4[e4];
        g_csr[atomicAdd(&g_cursor[t.x], 1)] = s.x;
        g_csr[atomicAdd(&g_cursor[t.y], 1)] = s.y;
        g_csr[atomicAdd(&g_cursor[t.z], 1)] = s.z;
        g_csr[atomicAdd(&g_cursor[t.w], 1)] = s.w;
    }
}

// ---------------------------------------------------------------------------
// 4) Z = diag(dinv) * (X @ W). One thread per node, W smem-broadcast,
//    packed f32x2 FFMA (halves FMA issue count vs scalar FFMA).
// ---------------------------------------------------------------------------
__global__ void __launch_bounds__(256) zgemm_kernel(const float* __restrict__ x,
                                                    const float* __restrict__ W) {
    __shared__ float Ws[D * D];      // 16 KB
    int tid = threadIdx.x;
    for (int i = tid; i < D * D; i += 256) Ws[i] = W[i];
    __syncthreads();

    int node = blockIdx.x * 256 + tid;
    if (node >= N_NODES) return;

    ull acc[32];                      // 64 output cols as 32 packed f32x2
    #pragma unroll
    for (int j = 0; j < 32; j++) acc[j] = 0ULL;   // {0.f, 0.f}

    const float4* xr = (const float4*)(x + (size_t)node * D);
    #pragma unroll 2
    for (int k4 = 0; k4 < 16; k4++) {
        float4 xv = xr[k4];
        float xs[4] = {xv.x, xv.y, xv.z, xv.w};
        #pragma unroll
        for (int kk = 0; kk < 4; kk++) {
            ull xk2 = pack2(xs[kk], xs[kk]);
            const ulonglong2* wrow = (const ulonglong2*)&Ws[(k4 * 4 + kk) * D];
            #pragma unroll
            for (int j = 0; j < 16; j++) {
                ulonglong2 w = wrow[j];           // broadcast LDS.128
                acc[2 * j]     = fma2(xk2, w.x, acc[2 * j]);
                acc[2 * j + 1] = fma2(xk2, w.y, acc[2 * j + 1]);
            }
        }
    }

    float dv = g_dinv[node];
    ull dv2 = pack2(dv, dv);
    ulonglong2* zr = (ulonglong2*)(g_z + (size_t)node * D);
    #pragma unroll
    for (int j = 0; j < 16; j++) {
        ulonglong2 o;
        o.x = mul2(acc[2 * j], dv2);
        o.y = mul2(acc[2 * j + 1], dv2);
        zr[j] = o;                                 // STG.128
    }
}

// ---------------------------------------------------------------------------
// 5) gather: out[t] = relu(dinv_t * sum_{s in N(t)} Z[s] + b)
//    16 lanes per node (lane c owns float4 chunk c), no shfl, no smem,
//    uniform loop per segment, unroll-4 for MLP.
// ---------------------------------------------------------------------------
__global__ void __launch_bounds__(256) gather_kernel(const float* __restrict__ b,
                                                     float* __restrict__ out) {
    int tid = threadIdx.x;
    int c = tid & 15;
    int node = blockIdx.x * 16 + (tid >> 4);   // 6250 * 16 = 100000 exactly

    int off = g_off[node];                      // broadcast within segment
    int deg = g_deg[node];
    const float4* __restrict__ z4 = (const float4*)g_z;

    float4 acc = make_float4(0.f, 0.f, 0.f, 0.f);
    int i = 0;
    for (; i + 4 <= deg; i += 4) {
        int i0 = g_csr[off + i];
        int i1 = g_csr[off + i + 1];
        int i2 = g_csr[off + i + 2];
        int i3 = g_csr[off + i + 3];
        float4 v0 = z4[i0 * 16 + c];
        float4 v1 = z4[i1 * 16 + c];
        float4 v2 = z4[i2 * 16 + c];
        float4 v3 = z4[i3 * 16 + c];
        acc.x += (v0.x + v1.x) + (v2.x + v3.x);
        acc.y += (v0.y + v1.y) + (v2.y + v3.y);
        acc.z += (v0.z + v1.z) + (v2.z + v3.z);
        acc.w += (v0.w + v1.w) + (v2.w + v3.w);
    }
    for (; i < deg; i++) {
        int i0 = g_csr[off + i];
        float4 v0 = z4[i0 * 16 + c];
        acc.x += v0.x; acc.y += v0.y; acc.z += v0.z; acc.w += v0.w;
    }

    float dn = g_dinv[node];
    float4 bias = ((const float4*)b)[c];
    float4 o;
    o.x = fmaxf(fmaf(acc.x, dn, bias.x), 0.f);
    o.y = fmaxf(fmaf(acc.y, dn, bias.y), 0.f);
    o.z = fmaxf(fmaf(acc.z, dn, bias.z), 0.f);
    o.w = fmaxf(fmaf(acc.w, dn, bias.w), 0.f);
    ((float4*)&out[(size_t)node * D])[c] = o;
}

// ---------------------------------------------------------------------------
// launch (7 kernels)
// ---------------------------------------------------------------------------
extern "C" void kernel_launch(void* const* d_in, const int* in_sizes, int n_in,
                              void* d_out, int out_size) {
    const float* x   = (const float*)d_in[0];   // [N_NODES, 64]
    const float* W   = (const float*)d_in[1];   // [64, 64]
    const float* b   = (const float*)d_in[2];   // [64]
    const int*   src = (const int*)d_in[3];     // [N_EDGES]
    const int*   tgt = (const int*)d_in[4];     // [N_EDGES]
    float* out = (float*)d_out;                 // [N_NODES, 64]

    zero_kernel<<<(N_NODES + 255) / 256, 256>>>();
    degree_kernel<<<(N_EDGES / 4 + 255) / 256, 256>>>((const int4*)tgt);
    scan1_kernel<<<NB_SCAN, SCAN_B>>>();
    scan3_kernel<<<(N_NODES + 255) / 256, 256>>>();
    fill_kernel<<<(N_EDGES / 4 + 255) / 256, 256>>>((const int4*)src, (const int4*)tgt);
    zgemm_kernel<<<(N_NODES + 255) / 256, 256>>>(x, W);
    gather_kernel<<<N_NODES / 16, 256>>>(b, out);
}